// round 14
// baseline (speedup 1.0000x reference)
#include <cuda_runtime.h>
#include <math.h>
#include <stdint.h>

#define N_LEVELS   16
#define HASH_MASK  0x7FFFFu
#define TABLE_SIZE (1u << 19)
#define NB         32768          // 32^3 sort buckets
#define NMAX       (1 << 20)

struct HashParams {
    int   res[N_LEVELS];
    float resf[N_LEVELS];
    float rcpf[N_LEVELS];   // RN32(1/res), matching XLA's div->mul rewrite
};

__device__ unsigned g_count[NB];    // zero at module load; re-zeroed by scan
__device__ unsigned g_cursor[NB];   // exclusive bucket offsets
__device__ int      g_perm[NMAX];
__device__ unsigned g_bkt[NMAX];    // (rank << 15) | bucket

__device__ __forceinline__ float clipf(float v)
{
    return fminf(fmaxf(v, -1.0f), 1.0f);
}

// 1 point per thread. atomicAdd return value = rank within bucket.
__global__ void hist_kernel(const float* __restrict__ x, int N)
{
    int n = blockIdx.x * blockDim.x + threadIdx.x;
    if (n >= N) return;
    float x0 = clipf(x[n * 3 + 0]);
    float x1 = clipf(x[n * 3 + 1]);
    float x2 = clipf(x[n * 3 + 2]);
    int c0 = min(31, (int)((x0 + 1.0f) * 16.0f));
    int c1 = min(31, (int)((x1 + 1.0f) * 16.0f));
    int c2 = min(31, (int)((x2 + 1.0f) * 16.0f));
    unsigned b = (unsigned)((c0 << 10) | (c1 << 5) | c2);
    unsigned rank = atomicAdd(&g_count[b], 1u);
    g_bkt[n] = (rank << 15) | b;
}

// Single block, 1024 threads: exclusive scan of 32768 counts via two-tier
// warp-shuffle scan. Re-zeroes g_count for the next graph replay.
__global__ void scan_kernel()
{
    __shared__ unsigned wsum[32];
    int t    = threadIdx.x;
    int lane = t & 31;
    int w    = t >> 5;

    unsigned loc[32], sum = 0;
#pragma unroll
    for (int i = 0; i < 32; i++) { loc[i] = g_count[t * 32 + i]; sum += loc[i]; }

    unsigned s = sum;
#pragma unroll
    for (int d = 1; d < 32; d <<= 1) {
        unsigned v = __shfl_up_sync(0xFFFFFFFFu, s, d);
        if (lane >= d) s += v;
    }
    if (lane == 31) wsum[w] = s;
    __syncthreads();

    if (w == 0) {
        unsigned ws = wsum[lane];
#pragma unroll
        for (int d = 1; d < 32; d <<= 1) {
            unsigned v = __shfl_up_sync(0xFFFFFFFFu, ws, d);
            if (lane >= d) ws += v;
        }
        wsum[lane] = ws;
    }
    __syncthreads();

    unsigned pre = (s - sum) + (w > 0 ? wsum[w - 1] : 0u);
#pragma unroll
    for (int i = 0; i < 32; i++) {
        g_cursor[t * 32 + i] = pre;
        pre += loc[i];
        g_count[t * 32 + i] = 0u;       // reset for next replay
    }
}

// Atomic-free scatter: pos = bucket_offset + rank (rank captured in hist).
__global__ void scatter_kernel(int N)
{
    int n = blockIdx.x * blockDim.x + threadIdx.x;
    if (n >= N) return;
    unsigned v   = g_bkt[n];
    unsigned pos = g_cursor[v & 0x7FFFu] + (v >> 15);
    g_perm[pos] = n;
}

// ---------------------------------------------------------------------------
// Main kernel: per-level results go straight into the smem transpose tile,
// collapsing live register state (acc[32] eliminated) -> higher occupancy.
// ---------------------------------------------------------------------------
__global__ __launch_bounds__(256)
void hash_encode_kernel(const float* __restrict__ x,
                        const float2* __restrict__ tables,
                        float* __restrict__ out,
                        int N, HashParams p)
{
    __shared__ float s_t[8][32 * 33];   // per-warp 32x32 transpose tile, pad 33

    int i   = blockIdx.x * blockDim.x + threadIdx.x;
    int wid = threadIdx.x >> 5;
    int lid = threadIdx.x & 31;

    bool valid = (i < N);
    int  ic    = valid ? i : (N - 1);
    int  n     = g_perm[ic];

    float xv[3] = {clipf(x[n * 3 + 0]), clipf(x[n * 3 + 1]), clipf(x[n * 3 + 2])};

    const unsigned PRIME[3] = {1u, 2654435761u, 805459861u};

    float* sw = s_t[wid];

#pragma unroll
    for (int l = 0; l < N_LEVELS; l++) {
        const int   resi = p.res[l];
        const float resf = p.resf[l];
        const float rcp  = p.rcpf[l];
        const float2* __restrict__ tb = tables + (size_t)l * TABLE_SIZE;

        unsigned term[3][2];
        float    wgt[3][2];
#pragma unroll
        for (int d = 0; d < 3; d++) {
            float c  = xv[d] * resf;
            float cf = floorf(c);
            float lc = c - cf;
            int   ci = (int)cf;
            wgt[d][0] = 1.0f - lc;
            wgt[d][1] = lc;
#pragma unroll
            for (int b = 0; b < 2; b++) {
                int m = ci + b;
                if (m < 0)     m += resi;
                if (m >= resi) m -= resi;
                // corners_f = m * RN32(1/res)  (XLA div->mul rewrite)
                float cfr = __fmul_rn((float)m, rcp);
                // q = trunc(RN(cfr + 1) * 131072), two separate roundings
                float t = __fmul_rn(__fadd_rn(cfr, 1.0f), 131072.0f);
                term[d][b] = (unsigned)t * PRIME[d];
            }
        }

        float2 f[8];
        float  w[8];
#pragma unroll
        for (int k = 0; k < 8; k++) {
            int b0 = (k >> 2) & 1, b1 = (k >> 1) & 1, b2 = k & 1;
            unsigned h = (term[0][b0] + term[1][b1] + term[2][b2]) & HASH_MASK;
            f[k] = __ldg(tb + h);
            w[k] = wgt[0][b0] * wgt[1][b1] * wgt[2][b2];
        }
        float a0 = 0.0f, a1 = 0.0f;
#pragma unroll
        for (int k = 0; k < 8; k++) { a0 += w[k] * f[k].x; a1 += w[k] * f[k].y; }

        // stage directly into the transpose tile: (lid*33 + c) % 32 banks
        // = (lid + c) % 32 -> conflict-free
        sw[lid * 33 + 2 * l]     = a0;
        sw[lid * 33 + 2 * l + 1] = a1;
    }

    __syncwarp();

    // ---- warp-cooperative transposed store --------------------------------
    int warp_i0 = i - lid;
    if (warp_i0 + 32 <= N) {
#pragma unroll 8
        for (int k = 0; k < 32; k++) {
            int nk = __shfl_sync(0xFFFFFFFFu, n, k);
            out[(size_t)nk * 32 + lid] = sw[k * 33 + lid];  // 1 line, 1 wf
        }
    } else if (valid) {
#pragma unroll
        for (int j = 0; j < 32; j++)
            out[(size_t)n * 32 + j] = sw[lid * 33 + j];
    }
}

// Fallback (no sort) for N > NMAX: identical math, direct indexing.
__global__ __launch_bounds__(256)
void hash_encode_direct(const float* __restrict__ x,
                        const float2* __restrict__ tables,
                        float4* __restrict__ out,
                        int N, HashParams p)
{
    int n = blockIdx.x * blockDim.x + threadIdx.x;
    if (n >= N) return;
    float xv[3] = {clipf(x[n*3+0]), clipf(x[n*3+1]), clipf(x[n*3+2])};
    const unsigned PRIME[3] = {1u, 2654435761u, 805459861u};
    float4* o = out + (size_t)n * 8;
#pragma unroll
    for (int g = 0; g < 4; g++) {
        float accg[8];
#pragma unroll
        for (int li = 0; li < 4; li++) {
            const int l = 4 * g + li;
            const int resi = p.res[l];
            const float resf = p.resf[l], rcp = p.rcpf[l];
            const float2* __restrict__ tb = tables + (size_t)l * TABLE_SIZE;
            unsigned term[3][2]; float wgt[3][2];
#pragma unroll
            for (int d = 0; d < 3; d++) {
                float c = xv[d] * resf, cf = floorf(c), lc = c - cf;
                int ci = (int)cf;
                wgt[d][0] = 1.0f - lc; wgt[d][1] = lc;
#pragma unroll
                for (int b = 0; b < 2; b++) {
                    int m = ci + b;
                    if (m < 0) m += resi;
                    if (m >= resi) m -= resi;
                    float cfr = __fmul_rn((float)m, rcp);
                    float t = __fmul_rn(__fadd_rn(cfr, 1.0f), 131072.0f);
                    term[d][b] = (unsigned)t * PRIME[d];
                }
            }
            float2 f[8]; float w[8];
#pragma unroll
            for (int k = 0; k < 8; k++) {
                int b0 = (k >> 2) & 1, b1 = (k >> 1) & 1, b2 = k & 1;
                unsigned h = (term[0][b0] + term[1][b1] + term[2][b2]) & HASH_MASK;
                f[k] = __ldg(tb + h);
                w[k] = wgt[0][b0] * wgt[1][b1] * wgt[2][b2];
            }
            float a0 = 0.0f, a1 = 0.0f;
#pragma unroll
            for (int k = 0; k < 8; k++) { a0 += w[k]*f[k].x; a1 += w[k]*f[k].y; }
            accg[2*li] = a0; accg[2*li+1] = a1;
        }
        o[2*g]   = make_float4(accg[0], accg[1], accg[2], accg[3]);
        o[2*g+1] = make_float4(accg[4], accg[5], accg[6], accg[7]);
    }
}

extern "C" void kernel_launch(void* const* d_in, const int* in_sizes, int n_in,
                              void* d_out, int out_size)
{
    const float*  x      = (const float*)d_in[0];
    const float2* tables = (const float2*)d_in[1];

    int N = in_sizes[0] / 3;

    HashParams p;
    for (int i = 0; i < N_LEVELS; i++) {
        double r = 16.0 * pow(32.0, (double)i / 15.0);  // same libm as Python ref
        p.res[i]  = (int)r;
        p.resf[i] = (float)p.res[i];
        p.rcpf[i] = 1.0f / p.resf[i];
    }

    int threads = 256;
    if (N <= NMAX) {
        hist_kernel<<<(N + threads - 1) / threads, threads>>>(x, N);
        scan_kernel<<<1, 1024>>>();
        scatter_kernel<<<(N + threads - 1) / threads, threads>>>(N);
        hash_encode_kernel<<<(N + threads - 1) / threads, threads>>>(
            x, tables, (float*)d_out, N, p);
    } else {
        hash_encode_direct<<<(N + threads - 1) / threads, threads>>>(
            x, tables, (float4*)d_out, N, p);
    }
}

// round 15
// speedup vs baseline: 1.8593x; 1.8593x over previous
#include <cuda_runtime.h>
#include <math.h>
#include <stdint.h>

#define N_LEVELS   16
#define HASH_MASK  0x7FFFFu
#define TABLE_SIZE (1u << 19)
#define NB         32768          // 32^3 sort buckets
#define NMAX       (1 << 20)

struct HashParams {
    int   res[N_LEVELS];
    float resf[N_LEVELS];
    float rcpf[N_LEVELS];   // RN32(1/res), matching XLA's div->mul rewrite
};

__device__ unsigned g_count[NB];    // zero at module load; re-zeroed by scan
__device__ unsigned g_cursor[NB];   // exclusive bucket offsets
__device__ int      g_perm[NMAX];
__device__ unsigned g_bkt[NMAX];    // (rank << 15) | bucket

__device__ __forceinline__ float clipf(float v)
{
    return fminf(fmaxf(v, -1.0f), 1.0f);
}

// 1 point per thread. atomicAdd return value = rank within bucket.
__global__ void hist_kernel(const float* __restrict__ x, int N)
{
    int n = blockIdx.x * blockDim.x + threadIdx.x;
    if (n >= N) return;
    float x0 = clipf(x[n * 3 + 0]);
    float x1 = clipf(x[n * 3 + 1]);
    float x2 = clipf(x[n * 3 + 2]);
    int c0 = min(31, (int)((x0 + 1.0f) * 16.0f));
    int c1 = min(31, (int)((x1 + 1.0f) * 16.0f));
    int c2 = min(31, (int)((x2 + 1.0f) * 16.0f));
    unsigned b = (unsigned)((c0 << 10) | (c1 << 5) | c2);
    unsigned rank = atomicAdd(&g_count[b], 1u);
    g_bkt[n] = (rank << 15) | b;
}

// Single block, 1024 threads: exclusive scan of 32768 counts via two-tier
// warp-shuffle scan. Re-zeroes g_count for the next graph replay.
__global__ void scan_kernel()
{
    __shared__ unsigned wsum[32];
    int t    = threadIdx.x;
    int lane = t & 31;
    int w    = t >> 5;

    unsigned loc[32], sum = 0;
#pragma unroll
    for (int i = 0; i < 32; i++) { loc[i] = g_count[t * 32 + i]; sum += loc[i]; }

    unsigned s = sum;
#pragma unroll
    for (int d = 1; d < 32; d <<= 1) {
        unsigned v = __shfl_up_sync(0xFFFFFFFFu, s, d);
        if (lane >= d) s += v;
    }
    if (lane == 31) wsum[w] = s;
    __syncthreads();

    if (w == 0) {
        unsigned ws = wsum[lane];
#pragma unroll
        for (int d = 1; d < 32; d <<= 1) {
            unsigned v = __shfl_up_sync(0xFFFFFFFFu, ws, d);
            if (lane >= d) ws += v;
        }
        wsum[lane] = ws;
    }
    __syncthreads();

    unsigned pre = (s - sum) + (w > 0 ? wsum[w - 1] : 0u);
#pragma unroll
    for (int i = 0; i < 32; i++) {
        g_cursor[t * 32 + i] = pre;
        pre += loc[i];
        g_count[t * 32 + i] = 0u;       // reset for next replay
    }
}

// Atomic-free scatter: pos = bucket_offset + rank (rank captured in hist).
__global__ void scatter_kernel(int N)
{
    int n = blockIdx.x * blockDim.x + threadIdx.x;
    if (n >= N) return;
    unsigned v   = g_bkt[n];
    unsigned pos = g_cursor[v & 0x7FFFu] + (v >> 15);
    g_perm[pos] = n;
}

// ---------------------------------------------------------------------------
// Main kernel: two half-passes (8 levels -> 16 features each) through a
// HALF-SIZE transpose tile (17.4KB/block vs 33.8KB) -> bigger L1D carveout
// (~158KB vs ~93KB) -> higher table hit rate -> higher l1tex throughput.
// ---------------------------------------------------------------------------
__global__ __launch_bounds__(256)
void hash_encode_kernel(const float* __restrict__ x,
                        const float2* __restrict__ tables,
                        float* __restrict__ out,
                        int N, HashParams p)
{
    __shared__ float s_t[8][32 * 17];   // per-warp 32 points x 16 feats, pad 17

    int i   = blockIdx.x * blockDim.x + threadIdx.x;
    int wid = threadIdx.x >> 5;
    int lid = threadIdx.x & 31;

    bool valid = (i < N);
    int  ic    = valid ? i : (N - 1);
    int  n     = g_perm[ic];

    float xv[3] = {clipf(x[n * 3 + 0]), clipf(x[n * 3 + 1]), clipf(x[n * 3 + 2])};

    const unsigned PRIME[3] = {1u, 2654435761u, 805459861u};

    float* sw      = s_t[wid];
    int    warp_i0 = i - lid;
    bool   full    = (warp_i0 + 32 <= N);
    int    sp      = lid >> 4;          // 0/1: which of 2 points this lane stores
    int    sf      = lid & 15;          // which feature within the half-row

#pragma unroll
    for (int half = 0; half < 2; half++) {
        float acc[16];

#pragma unroll
        for (int li = 0; li < 8; li++) {
            const int   l    = 8 * half + li;
            const int   resi = p.res[l];
            const float resf = p.resf[l];
            const float rcp  = p.rcpf[l];
            const float2* __restrict__ tb = tables + (size_t)l * TABLE_SIZE;

            unsigned term[3][2];
            float    wgt[3][2];
#pragma unroll
            for (int d = 0; d < 3; d++) {
                float c  = xv[d] * resf;
                float cf = floorf(c);
                float lc = c - cf;
                int   ci = (int)cf;
                wgt[d][0] = 1.0f - lc;
                wgt[d][1] = lc;
#pragma unroll
                for (int b = 0; b < 2; b++) {
                    int m = ci + b;
                    if (m < 0)     m += resi;
                    if (m >= resi) m -= resi;
                    // corners_f = m * RN32(1/res)  (XLA div->mul rewrite)
                    float cfr = __fmul_rn((float)m, rcp);
                    // q = trunc(RN(cfr + 1) * 131072), two separate roundings
                    float t = __fmul_rn(__fadd_rn(cfr, 1.0f), 131072.0f);
                    term[d][b] = (unsigned)t * PRIME[d];
                }
            }

            float2 f[8];
            float  w[8];
#pragma unroll
            for (int k = 0; k < 8; k++) {
                int b0 = (k >> 2) & 1, b1 = (k >> 1) & 1, b2 = k & 1;
                unsigned h = (term[0][b0] + term[1][b1] + term[2][b2]) & HASH_MASK;
                f[k] = __ldg(tb + h);
                w[k] = wgt[0][b0] * wgt[1][b1] * wgt[2][b2];
            }
            float a0 = 0.0f, a1 = 0.0f;
#pragma unroll
            for (int k = 0; k < 8; k++) { a0 += w[k] * f[k].x; a1 += w[k] * f[k].y; }
            acc[2 * li]     = a0;
            acc[2 * li + 1] = a1;
        }

        if (full) {
            // stage this half into the tile (stride 17, gcd(17,32)=1: clean)
#pragma unroll
            for (int j = 0; j < 16; j++)
                sw[lid * 17 + j] = acc[j];
            __syncwarp();

            // 2 points per instruction: lanes 0-15 -> point k, 16-31 -> k+1
#pragma unroll 8
            for (int k = 0; k < 32; k += 2) {
                int nk = __shfl_sync(0xFFFFFFFFu, n, k + sp);
                out[(size_t)nk * 32 + half * 16 + sf] = sw[(k + sp) * 17 + sf];
            }
            __syncwarp();   // tile reused by next half
        } else if (valid) {
#pragma unroll
            for (int j = 0; j < 16; j++)
                out[(size_t)n * 32 + half * 16 + j] = acc[j];
        }
    }
}

// Fallback (no sort) for N > NMAX: identical math, direct indexing.
__global__ __launch_bounds__(256)
void hash_encode_direct(const float* __restrict__ x,
                        const float2* __restrict__ tables,
                        float4* __restrict__ out,
                        int N, HashParams p)
{
    int n = blockIdx.x * blockDim.x + threadIdx.x;
    if (n >= N) return;
    float xv[3] = {clipf(x[n*3+0]), clipf(x[n*3+1]), clipf(x[n*3+2])};
    const unsigned PRIME[3] = {1u, 2654435761u, 805459861u};
    float4* o = out + (size_t)n * 8;
#pragma unroll
    for (int g = 0; g < 4; g++) {
        float accg[8];
#pragma unroll
        for (int li = 0; li < 4; li++) {
            const int l = 4 * g + li;
            const int resi = p.res[l];
            const float resf = p.resf[l], rcp = p.rcpf[l];
            const float2* __restrict__ tb = tables + (size_t)l * TABLE_SIZE;
            unsigned term[3][2]; float wgt[3][2];
#pragma unroll
            for (int d = 0; d < 3; d++) {
                float c = xv[d] * resf, cf = floorf(c), lc = c - cf;
                int ci = (int)cf;
                wgt[d][0] = 1.0f - lc; wgt[d][1] = lc;
#pragma unroll
                for (int b = 0; b < 2; b++) {
                    int m = ci + b;
                    if (m < 0) m += resi;
                    if (m >= resi) m -= resi;
                    float cfr = __fmul_rn((float)m, rcp);
                    float t = __fmul_rn(__fadd_rn(cfr, 1.0f), 131072.0f);
                    term[d][b] = (unsigned)t * PRIME[d];
                }
            }
            float2 f[8]; float w[8];
#pragma unroll
            for (int k = 0; k < 8; k++) {
                int b0 = (k >> 2) & 1, b1 = (k >> 1) & 1, b2 = k & 1;
                unsigned h = (term[0][b0] + term[1][b1] + term[2][b2]) & HASH_MASK;
                f[k] = __ldg(tb + h);
                w[k] = wgt[0][b0] * wgt[1][b1] * wgt[2][b2];
            }
            float a0 = 0.0f, a1 = 0.0f;
#pragma unroll
            for (int k = 0; k < 8; k++) { a0 += w[k]*f[k].x; a1 += w[k]*f[k].y; }
            accg[2*li] = a0; accg[2*li+1] = a1;
        }
        o[2*g]   = make_float4(accg[0], accg[1], accg[2], accg[3]);
        o[2*g+1] = make_float4(accg[4], accg[5], accg[6], accg[7]);
    }
}

extern "C" void kernel_launch(void* const* d_in, const int* in_sizes, int n_in,
                              void* d_out, int out_size)
{
    const float*  x      = (const float*)d_in[0];
    const float2* tables = (const float2*)d_in[1];

    int N = in_sizes[0] / 3;

    HashParams p;
    for (int i = 0; i < N_LEVELS; i++) {
        double r = 16.0 * pow(32.0, (double)i / 15.0);  // same libm as Python ref
        p.res[i]  = (int)r;
        p.resf[i] = (float)p.res[i];
        p.rcpf[i] = 1.0f / p.resf[i];
    }

    int threads = 256;
    if (N <= NMAX) {
        hist_kernel<<<(N + threads - 1) / threads, threads>>>(x, N);
        scan_kernel<<<1, 1024>>>();
        scatter_kernel<<<(N + threads - 1) / threads, threads>>>(N);
        hash_encode_kernel<<<(N + threads - 1) / threads, threads>>>(
            x, tables, (float*)d_out, N, p);
    } else {
        hash_encode_direct<<<(N + threads - 1) / threads, threads>>>(
            x, tables, (float4*)d_out, N, p);
    }
}